// round 4
// baseline (speedup 1.0000x reference)
#include <cuda_runtime.h>
#include <cstdint>

// Problem constants (fixed shapes per reference)
constexpr int B_ = 8;
constexpr int S_ = 4096;
constexpr int D_ = 2048;
constexpr int R_ = 4;
// Effective: per batch b, only adapters j = 4b..4b+3 contribute, weight 8/32 = 0.25.

constexpr int MT = 128;         // rows per stage-1 block
constexpr int KT = 32;          // K tile
constexpr int XS_STRIDE = 130;  // padded k-major x tile stride
constexpr int SROWS = 64;       // rows per stage-2 block

// Scratch: h[b*S + s][16]  (c = j*4 + r), 2 MB -> L2-resident
__device__ float g_h[(size_t)B_ * S_ * 16];

// ---- packed f32x2 helpers (sm_100+ PTX) ----
__device__ __forceinline__ unsigned long long fma2(unsigned long long a,
                                                   unsigned long long b,
                                                   unsigned long long c) {
    unsigned long long d;
    asm("fma.rn.f32x2 %0, %1, %2, %3;" : "=l"(d) : "l"(a), "l"(b), "l"(c));
    return d;
}
__device__ __forceinline__ unsigned long long pack2(float lo, float hi) {
    unsigned long long d;
    asm("mov.b64 %0, {%1, %2};" : "=l"(d) : "f"(lo), "f"(hi));
    return d;
}
__device__ __forceinline__ float2 unpack2(unsigned long long v) {
    float2 r;
    asm("mov.b64 {%0, %1}, %2;" : "=f"(r.x), "=f"(r.y) : "l"(v));
    return r;
}

// ============================================================================
// Stage 1: h[row][c] = sum_d x[row][d] * Bc[d][c]
//   Bc[d][j*4+r] = adapter_b[(4b+j)*D*R + d*R + r]
// Block: 256 threads, 128 rows x 16 cols, K loop in tiles of 32.
// Thread tile: 2 rows x 4 cols (2 f32x2 col-pairs).
// ============================================================================
__global__ __launch_bounds__(256) void lora_stage1(
    const float* __restrict__ x, const float* __restrict__ ab) {
    __shared__ float xs[KT * XS_STRIDE];  // xs[k*130 + m], k-major
    __shared__ float bs[KT][16];

    const int tid = threadIdx.x;
    const int row0 = blockIdx.x * MT;  // global row = b*S + s
    const int b = row0 / S_;

    // compute mapping: rg in [0,64) -> 2 rows, cg in [0,4) -> 4 cols
    const int rg = tid >> 2;
    const int cg = tid & 3;
    // loader mapping: lrow in [0,32), lk in [0,8) (4 floats each -> 32 k)
    const int lrow = tid >> 3;
    const int lk = tid & 7;

    const float* bbase = ab + (size_t)(4 * b) * D_ * R_;
    const float* xload = x + (size_t)(row0 + lrow) * D_ + lk * 4;

    unsigned long long acc00 = 0ull, acc01 = 0ull, acc10 = 0ull, acc11 = 0ull;

    for (int k0 = 0; k0 < D_; k0 += KT) {
        // B tile: 32 k x 16 c ; threads 0..127, one float4 each
        if (tid < 128) {
            const int kk = tid >> 2;
            const int j = tid & 3;
            float4 v = *(const float4*)(bbase + (size_t)j * (D_ * R_) +
                                        (size_t)(k0 + kk) * R_);
            *(float4*)&bs[kk][j * 4] = v;
        }
        // x tile: 128 rows x 32 k, transposed to k-major
#pragma unroll
        for (int rr = 0; rr < 4; rr++) {
            float4 v = *(const float4*)(xload + (size_t)rr * 32 * D_ + k0);
            const int m = lrow + rr * 32;
            const int kb = lk * 4;
            xs[(kb + 0) * XS_STRIDE + m] = v.x;
            xs[(kb + 1) * XS_STRIDE + m] = v.y;
            xs[(kb + 2) * XS_STRIDE + m] = v.z;
            xs[(kb + 3) * XS_STRIDE + m] = v.w;
        }
        __syncthreads();

#pragma unroll
        for (int kk = 0; kk < KT; kk++) {
            float2 xv = *(const float2*)&xs[kk * XS_STRIDE + rg * 2];
            unsigned long long b01 =
                *(const unsigned long long*)&bs[kk][cg * 4];
            unsigned long long b23 =
                *(const unsigned long long*)&bs[kk][cg * 4 + 2];
            unsigned long long x0 = pack2(xv.x, xv.x);
            unsigned long long x1 = pack2(xv.y, xv.y);
            acc00 = fma2(x0, b01, acc00);
            acc01 = fma2(x0, b23, acc01);
            acc10 = fma2(x1, b01, acc10);
            acc11 = fma2(x1, b23, acc11);
        }
        __syncthreads();
    }

    // write h: rows row0 + rg*2 + {0,1}, cols cg*4..cg*4+3
    {
        float2 lo = unpack2(acc00);
        float2 hi = unpack2(acc01);
        float4 v = make_float4(lo.x, lo.y, hi.x, hi.y);
        *(float4*)(g_h + (size_t)(row0 + rg * 2 + 0) * 16 + cg * 4) = v;
    }
    {
        float2 lo = unpack2(acc10);
        float2 hi = unpack2(acc11);
        float4 v = make_float4(lo.x, lo.y, hi.x, hi.y);
        *(float4*)(g_h + (size_t)(row0 + rg * 2 + 1) * 16 + cg * 4) = v;
    }
}

// ============================================================================
// Stage 2: out[row][d] = relu( 0.25 * sum_c h[row][c] * Ac[c][d] )
//   Ac[j*4+r][d] = adapter_a[(4b+j)*R*D + r*D + d]
// Block: 512 threads, each owns 4 consecutive d (A slice in registers),
// loops SROWS=64 rows with h broadcast from smem (pre-duplicated, pre-scaled).
// ============================================================================
__global__ __launch_bounds__(512) void lora_stage2(
    const float* __restrict__ aa, float* __restrict__ out) {
    __shared__ float2 hs[SROWS][16];  // (0.25*h, 0.25*h) pairs

    const int tid = threadIdx.x;
    const int b = blockIdx.y;
    const int s0 = blockIdx.x * SROWS;
    const size_t row0 = (size_t)b * S_ + s0;
    const int d0 = tid * 4;

    // Load A slice into registers: 16 c x 4 d -> 16 x 2 f32x2
    unsigned long long areg[16][2];
#pragma unroll
    for (int j = 0; j < 4; j++) {
#pragma unroll
        for (int r = 0; r < 4; r++) {
            float4 v = *(const float4*)(aa + (size_t)(4 * b + j) * (R_ * D_) +
                                        (size_t)r * D_ + d0);
            areg[j * 4 + r][0] = pack2(v.x, v.y);
            areg[j * 4 + r][1] = pack2(v.z, v.w);
        }
    }

    // Stage h tile into smem, duplicated and pre-scaled by 0.25
    for (int i = tid; i < SROWS * 16; i += 512) {
        float v = g_h[row0 * 16 + i] * 0.25f;
        ((float2*)hs)[i] = make_float2(v, v);
    }
    __syncthreads();

    for (int rr = 0; rr < SROWS; rr++) {
        unsigned long long acc0 = 0ull, acc1 = 0ull;
#pragma unroll
        for (int c = 0; c < 16; c++) {
            unsigned long long hv = *(const unsigned long long*)&hs[rr][c];
            acc0 = fma2(hv, areg[c][0], acc0);
            acc1 = fma2(hv, areg[c][1], acc1);
        }
        float2 v0 = unpack2(acc0);
        float2 v1 = unpack2(acc1);
        float4 o;
        o.x = fmaxf(v0.x, 0.0f);
        o.y = fmaxf(v0.y, 0.0f);
        o.z = fmaxf(v1.x, 0.0f);
        o.w = fmaxf(v1.y, 0.0f);
        *(float4*)(out + (row0 + rr) * D_ + d0) = o;
    }
}

extern "C" void kernel_launch(void* const* d_in, const int* in_sizes, int n_in,
                              void* d_out, int out_size) {
    const float* x = (const float*)d_in[0];
    const float* ab = (const float*)d_in[1];
    const float* aa = (const float*)d_in[2];
    float* out = (float*)d_out;

    lora_stage1<<<(B_ * S_) / MT, 256>>>(x, ab);

    dim3 g2(S_ / SROWS, B_);
    lora_stage2<<<g2, 512>>>(aa, out);
}

// round 5
// speedup vs baseline: 1.3806x; 1.3806x over previous
#include <cuda_runtime.h>
#include <cstdint>

// Problem constants (fixed shapes per reference)
constexpr int B_ = 8;
constexpr int S_ = 4096;
constexpr int D_ = 2048;
constexpr int R_ = 4;
// Effective math: out[b,s,:] = relu(0.25 * (x[b,s,:] @ Bc_b) @ Ac_b),
// Bc_b = concat(adapter_b[4b..4b+3]) -> [2048,16], Ac_b -> [16,2048].

// ---- Stage 1 config ----
constexpr int KSPLIT = 4;
constexpr int KRANGE = D_ / KSPLIT;   // 512 k per block
constexpr int S1_THREADS = 128;
constexpr int S1_ROWS = 256;          // 2 rows per thread

// ---- Stage 2 config ----
constexpr int SROWS = 64;
constexpr int S2_THREADS = 256;       // each thread owns 4 d; block covers 1024 d

// Partial h: [split][row][16] -> 8 MB (L2-resident)
__device__ float g_hp[KSPLIT][(size_t)B_ * S_ * 16];

// ---- packed f32x2 helpers (sm_100+ PTX) ----
__device__ __forceinline__ unsigned long long fma2(unsigned long long a,
                                                   unsigned long long b,
                                                   unsigned long long c) {
    unsigned long long d;
    asm("fma.rn.f32x2 %0, %1, %2, %3;" : "=l"(d) : "l"(a), "l"(b), "l"(c));
    return d;
}
__device__ __forceinline__ unsigned long long add2(unsigned long long a,
                                                   unsigned long long b) {
    unsigned long long d;
    asm("add.rn.f32x2 %0, %1, %2;" : "=l"(d) : "l"(a), "l"(b));
    return d;
}
__device__ __forceinline__ unsigned long long pack2(float lo, float hi) {
    unsigned long long d;
    asm("mov.b64 %0, {%1, %2};" : "=l"(d) : "f"(lo), "f"(hi));
    return d;
}
__device__ __forceinline__ float2 unpack2(unsigned long long v) {
    float2 r;
    asm("mov.b64 {%0, %1}, %2;" : "=f"(r.x), "=f"(r.y) : "l"(v));
    return r;
}

// ============================================================================
// Stage 1: h_partial[split][row][c] = sum_{k in split range} x[row][k]*Bc[k][c]
// 128 threads, 2 rows/thread (rows tid and tid+128), 16 cols each.
// Whole B k-range (512x16 = 32KB) preloaded to smem once; x streamed from
// gmem in registers (no smem transpose, no per-tile syncs).
// ============================================================================
__global__ __launch_bounds__(S1_THREADS, 3) void lora_stage1(
    const float* __restrict__ x, const float* __restrict__ ab) {
    __shared__ float bs[KRANGE][16];  // 32 KB

    const int tid = threadIdx.x;
    const int row0 = blockIdx.x * S1_ROWS;
    const int split = blockIdx.y;
    const int kbase = split * KRANGE;
    const int b = row0 / S_;

    // Preload B tile: bs[k][j*4+r] = adapter_b[4b+j][kbase+k][r]
    const float* bbase = ab + (size_t)(4 * b) * D_ * R_;
    for (int t = tid; t < KRANGE * 4; t += S1_THREADS) {
        const int j = t / KRANGE;  // adapter slot within batch
        const int k = t % KRANGE;  // consecutive k across threads -> coalesced
        float4 v = *(const float4*)(bbase + (size_t)j * (D_ * R_) +
                                    (size_t)(kbase + k) * R_);
        *(float4*)&bs[k][j * 4] = v;
    }
    __syncthreads();

    const float* xr0 = x + (size_t)(row0 + tid) * D_ + kbase;
    const float* xr1 = xr0 + (size_t)128 * D_;

    unsigned long long acc0[8], acc1[8];
#pragma unroll
    for (int c = 0; c < 8; c++) { acc0[c] = 0ull; acc1[c] = 0ull; }

    // Process 8 k per iteration; prefetch next 8 k.
    float4 xa0 = *(const float4*)(xr0 + 0);
    float4 xa1 = *(const float4*)(xr0 + 4);
    float4 xb0 = *(const float4*)(xr1 + 0);
    float4 xb1 = *(const float4*)(xr1 + 4);

    for (int k0 = 0; k0 < KRANGE; k0 += 8) {
        const int kn = (k0 + 8 < KRANGE) ? (k0 + 8) : k0;  // harmless reload
        float4 na0 = *(const float4*)(xr0 + kn + 0);
        float4 na1 = *(const float4*)(xr0 + kn + 4);
        float4 nb0 = *(const float4*)(xr1 + kn + 0);
        float4 nb1 = *(const float4*)(xr1 + kn + 4);

        const float* xa = (const float*)&xa0;  // xa0,xa1 contiguous? not guaranteed
        // use explicit arrays instead:
        float xav[8] = {xa0.x, xa0.y, xa0.z, xa0.w, xa1.x, xa1.y, xa1.z, xa1.w};
        float xbv[8] = {xb0.x, xb0.y, xb0.z, xb0.w, xb1.x, xb1.y, xb1.z, xb1.w};
        (void)xa;

#pragma unroll
        for (int kk = 0; kk < 8; kk++) {
            const unsigned long long x0 = pack2(xav[kk], xav[kk]);
            const unsigned long long x1 = pack2(xbv[kk], xbv[kk]);
            const ulonglong2* brow = (const ulonglong2*)&bs[k0 + kk][0];
            ulonglong2 bp0 = brow[0];
            ulonglong2 bp1 = brow[1];
            ulonglong2 bp2 = brow[2];
            ulonglong2 bp3 = brow[3];
            acc0[0] = fma2(x0, bp0.x, acc0[0]);
            acc0[1] = fma2(x0, bp0.y, acc0[1]);
            acc0[2] = fma2(x0, bp1.x, acc0[2]);
            acc0[3] = fma2(x0, bp1.y, acc0[3]);
            acc0[4] = fma2(x0, bp2.x, acc0[4]);
            acc0[5] = fma2(x0, bp2.y, acc0[5]);
            acc0[6] = fma2(x0, bp3.x, acc0[6]);
            acc0[7] = fma2(x0, bp3.y, acc0[7]);
            acc1[0] = fma2(x1, bp0.x, acc1[0]);
            acc1[1] = fma2(x1, bp0.y, acc1[1]);
            acc1[2] = fma2(x1, bp1.x, acc1[2]);
            acc1[3] = fma2(x1, bp1.y, acc1[3]);
            acc1[4] = fma2(x1, bp2.x, acc1[4]);
            acc1[5] = fma2(x1, bp2.y, acc1[5]);
            acc1[6] = fma2(x1, bp3.x, acc1[6]);
            acc1[7] = fma2(x1, bp3.y, acc1[7]);
        }
        xa0 = na0; xa1 = na1; xb0 = nb0; xb1 = nb1;
    }

    // Write partial h rows (16 floats each) as 2x STG.128 per row
    float* o0 = g_hp[split] + (size_t)(row0 + tid) * 16;
    float* o1 = g_hp[split] + (size_t)(row0 + tid + 128) * 16;
    ((ulonglong2*)o0)[0] = make_ulonglong2(acc0[0], acc0[1]);
    ((ulonglong2*)o0)[1] = make_ulonglong2(acc0[2], acc0[3]);
    ((ulonglong2*)o0)[2] = make_ulonglong2(acc0[4], acc0[5]);
    ((ulonglong2*)o0)[3] = make_ulonglong2(acc0[6], acc0[7]);
    ((ulonglong2*)o1)[0] = make_ulonglong2(acc1[0], acc1[1]);
    ((ulonglong2*)o1)[1] = make_ulonglong2(acc1[2], acc1[3]);
    ((ulonglong2*)o1)[2] = make_ulonglong2(acc1[4], acc1[5]);
    ((ulonglong2*)o1)[3] = make_ulonglong2(acc1[6], acc1[7]);
}

// ============================================================================
// Stage 2: out[row][d] = relu( 0.25 * sum_c h[row][c] * Ac[c][d] )
// 256 threads, each owns 4 consecutive d (A slice in regs); block covers
// 1024 d x 64 rows. h tile summed over 4 partials, pre-scaled, duplicated
// into smem pairs; inner loop = 8 LDS.128 broadcast + 32 fma2 in 4 chains.
// ============================================================================
__global__ __launch_bounds__(S2_THREADS) void lora_stage2(
    const float* __restrict__ aa, float* __restrict__ out) {
    __shared__ float2 hs[SROWS][16];  // duplicated (0.25*h, 0.25*h) pairs, 8KB

    const int tid = threadIdx.x;
    const int b = blockIdx.z;
    const int s0 = blockIdx.x * SROWS;
    const size_t row0 = (size_t)b * S_ + s0;
    const int d0 = blockIdx.y * 1024 + tid * 4;

    // A slice into registers: 16 c x 4 d -> 16 x 2 f32x2
    unsigned long long areg[16][2];
#pragma unroll
    for (int j = 0; j < 4; j++) {
#pragma unroll
        for (int r = 0; r < 4; r++) {
            float4 v = *(const float4*)(aa + (size_t)(4 * b + j) * (R_ * D_) +
                                        (size_t)r * D_ + d0);
            areg[j * 4 + r][0] = pack2(v.x, v.y);
            areg[j * 4 + r][1] = pack2(v.z, v.w);
        }
    }

    // Fill hs: sum 4 partials, scale 0.25, duplicate into pairs
    const float2* hp0 = (const float2*)(g_hp[0] + row0 * 16);
    const float2* hp1 = (const float2*)(g_hp[1] + row0 * 16);
    const float2* hp2 = (const float2*)(g_hp[2] + row0 * 16);
    const float2* hp3 = (const float2*)(g_hp[3] + row0 * 16);
    for (int i = tid; i < SROWS * 8; i += S2_THREADS) {
        float2 v0 = hp0[i], v1 = hp1[i], v2 = hp2[i], v3 = hp3[i];
        const float a = (v0.x + v1.x + v2.x + v3.x) * 0.25f;
        const float c = (v0.y + v1.y + v2.y + v3.y) * 0.25f;
        const int rr = i >> 3;
        const int cp = i & 7;
        hs[rr][2 * cp + 0] = make_float2(a, a);
        hs[rr][2 * cp + 1] = make_float2(c, c);
    }
    __syncthreads();

    float* orow = out + row0 * D_ + d0;
    for (int rr = 0; rr < SROWS; rr++) {
        unsigned long long a0 = 0ull, a1 = 0ull, a2 = 0ull, a3 = 0ull;
#pragma unroll
        for (int c = 0; c < 16; c += 2) {
            ulonglong2 hv = *(const ulonglong2*)&hs[rr][c];
            a0 = fma2(hv.x, areg[c + 0][0], a0);
            a1 = fma2(hv.x, areg[c + 0][1], a1);
            a2 = fma2(hv.y, areg[c + 1][0], a2);
            a3 = fma2(hv.y, areg[c + 1][1], a3);
        }
        const unsigned long long s01 = add2(a0, a2);
        const unsigned long long s23 = add2(a1, a3);
        float2 v0 = unpack2(s01);
        float2 v1 = unpack2(s23);
        float4 o;
        o.x = fmaxf(v0.x, 0.0f);
        o.y = fmaxf(v0.y, 0.0f);
        o.z = fmaxf(v1.x, 0.0f);
        o.w = fmaxf(v1.y, 0.0f);
        *(float4*)(orow + (size_t)rr * D_) = o;
    }
}

extern "C" void kernel_launch(void* const* d_in, const int* in_sizes, int n_in,
                              void* d_out, int out_size) {
    const float* x = (const float*)d_in[0];
    const float* ab = (const float*)d_in[1];
    const float* aa = (const float*)d_in[2];
    float* out = (float*)d_out;

    dim3 g1((B_ * S_) / S1_ROWS, KSPLIT);  // (128, 4) = 512 blocks
    lora_stage1<<<g1, S1_THREADS>>>(x, ab);

    dim3 g2(S_ / SROWS, D_ / (S2_THREADS * 4), B_);  // (64, 2, 8) = 1024 blocks
    lora_stage2<<<g2, S2_THREADS>>>(aa, out);
}